// round 9
// baseline (speedup 1.0000x reference)
#include <cuda_runtime.h>

// L2LossWithRebalancing — GB300 sm_103a, round 9.
// Fine 512x512 Voronoi LUT (0.5-unit cells): halves the multi-candidate
// (scattered-load) pixel fraction. 4-byte float-encoded LUT entries:
//   v > 0      : single candidate, v == class weight (fast path, one load)
//   -4.5<=v<0  : cnt = -v in {2,3,4}; 4 sentinel-padded float4 slots
//   v < -4.5   : pathological; exact full scan of all 313 centers
// Loss: 4 pixels/thread, float4 coalesced pixel loads, batched LUT loads.
// Deterministic fixed-point u64 atomic reduction, graph-replay safe.

#define K_REAL 313
#define GRIDW 512
#define NCELLS (GRIDW * GRIDW)
#define CAPI 4
#define SCAP 48
#define NPIX (16 * 256 * 256)
#define CH_STRIDE 65536
#define IMG_STRIDE 131072
#define LTHREADS 256
#define PXT 4
#define LBLOCKS (NPIX / (LTHREADS * PXT))   // 1024
#define BTHREADS 256                        // 16x16 cells per supercell
#define BBLOCKS 1024                        // 32x32 supercells
#define FIXSCALE 1048576.0                  // 2^20

__device__ float              g_lut[NCELLS];            // 1 MB, float-encoded
__device__ float4             g_cdata[NCELLS * CAPI];   // multi-cell slots only
__device__ float4             g_ctr[K_REAL];            // (2ca,2cb,-|c|^2,w)
__device__ unsigned long long g_acc;                    // zero-init; self-reset
__device__ unsigned int       g_tickets;                // zero-init; wraps

// ---------------------------------------------------------------------------
// Build: block = 16x16-cell supercell, thread = cell.
// score s_k(x) = 2*c_k.x - |c_k|^2 ;  d^2(x,c_k) = |x|^2 - s_k(x).
// ---------------------------------------------------------------------------
__global__ __launch_bounds__(BTHREADS)
void build_kernel(const float* __restrict__ centers,
                  const float* __restrict__ cw) {
    __shared__ float4 sB[K_REAL];
    __shared__ float4 scand[SCAP];
    __shared__ float  swarp[BTHREADS / 32];
    __shared__ float  s_sth;
    __shared__ int    s_cnt;

    const int t = threadIdx.x;
    for (int i = t; i < K_REAL; i += BTHREADS) {
        float ca = centers[2 * i];
        float cb = centers[2 * i + 1];
        float4 v = make_float4(2.f * ca, 2.f * cb,
                               -(ca * ca + cb * cb), cw[i]);
        sB[i] = v;
        if (blockIdx.x == 0) g_ctr[i] = v;
    }
    __syncthreads();

    // supercell center (cell size 0.5; cell center x = 0.5*ix - 127.75)
    const int sx = blockIdx.x & 31;
    const int sy = blockIdx.x >> 5;
    const float sccx = 8.f * sx - 124.f;
    const float sccy = 8.f * sy - 124.f;
    const float scc2 = sccx * sccx + sccy * sccy;

    // block-cooperative max score at supercell center
    float m = -1e30f;
    for (int i = t; i < K_REAL; i += BTHREADS) {
        float4 c = sB[i];
        m = fmaxf(m, fmaf(c.x, sccx, fmaf(c.y, sccy, c.z)));
    }
    #pragma unroll
    for (int off = 16; off; off >>= 1)
        m = fmaxf(m, __shfl_xor_sync(0xFFFFFFFFu, m, off));
    if ((t & 31) == 0) swarp[t >> 5] = m;
    __syncthreads();
    if (t == 0) {
        float mm = swarp[0];
        #pragma unroll
        for (int wnum = 1; wnum < BTHREADS / 32; wnum++)
            mm = fmaxf(mm, swarp[wnum]);
        float d2min = fmaxf(scc2 - mm, 0.f);
        // 2 * 3.75*sqrt2 (scc->cellcenter) + 0.7071 (cell diag) + margin
        float T = sqrtf(d2min) + 11.4f;
        s_sth = scc2 - T * T;
    }
    __syncthreads();

    // deterministic candidate compaction: warp 0 only, index-ordered
    if (t < 32) {
        const float sth_sc = s_sth;
        int cnt = 0;
        for (int base = 0; base < K_REAL; base += 32) {
            const int i = base + t;
            bool pred = false;
            float4 c = make_float4(0.f, 0.f, 0.f, 0.f);
            if (i < K_REAL) {
                c = sB[i];
                pred = (fmaf(c.x, sccx, fmaf(c.y, sccy, c.z)) >= sth_sc);
            }
            const unsigned mask = __ballot_sync(0xFFFFFFFFu, pred);
            if (pred) {
                const int pos = cnt + __popc(mask & ((1u << t) - 1u));
                if (pos < SCAP) scand[pos] = c;
            }
            cnt += __popc(mask);
        }
        if (t == 0) s_cnt = cnt;
    }
    __syncthreads();

    const float4* list;
    int n;
    if (s_cnt <= SCAP) { list = scand; n = s_cnt; }
    else               { list = sB;    n = K_REAL; }   // overflow fallback

    // per-cell passes over the short list
    const int ix = 16 * sx + (t & 15);
    const int iy = 16 * sy + (t >> 4);
    const float ccx = 0.5f * (float)ix - 127.75f;
    const float ccy = 0.5f * (float)iy - 127.75f;
    const float cc2 = ccx * ccx + ccy * ccy;

    float smax = -1e30f;
    for (int k = 0; k < n; k++) {
        float4 c = list[k];
        smax = fmaxf(smax, fmaf(c.x, ccx, fmaf(c.y, ccy, c.z)));
    }
    float d2min = fmaxf(cc2 - smax, 0.f);
    float T = sqrtf(d2min) + 0.7271f;      // 0.5*sqrt2 cell diag + margin
    const float sth = cc2 - T * T;

    const int cell = (iy << 9) | ix;
    int cnt = 0;
    float w0 = 0.f;
    float4* slot = &g_cdata[cell * CAPI];
    for (int k = 0; k < n; k++) {
        float4 c = list[k];
        float s = fmaf(c.x, ccx, fmaf(c.y, ccy, c.z));
        if (s >= sth) {
            if (cnt < CAPI) slot[cnt] = c;
            if (cnt == 0) w0 = c.w;
            cnt++;
        }
    }
    float ev;
    if (cnt == 1) {
        ev = w0;                                   // positive weight
    } else if (cnt <= CAPI) {
        const float4 sentinel = make_float4(0.f, 0.f, -1e30f, 0.f);
        for (int j = cnt; j < CAPI; j++) slot[j] = sentinel;
        ev = -(float)cnt;                          // -2..-4
    } else {
        ev = -1000.f;                              // full-scan fallback
    }
    g_lut[cell] = ev;
}

// ---------------------------------------------------------------------------
// Loss: 4 pixels/thread, phase-split, float4 coalesced pixel loads.
// ---------------------------------------------------------------------------
__global__ __launch_bounds__(LTHREADS)
void loss_kernel(const float* __restrict__ pred,
                 const float* __restrict__ target,
                 float* __restrict__ out) {
    __shared__ float sred[LTHREADS / 32];

    const int t   = threadIdx.x;
    const int tid = blockIdx.x * LTHREADS + t;
    const int p   = tid * PXT;
    const int b   = p >> 16;
    const int r   = p & 65535;

    const float* tb = target + (size_t)b * IMG_STRIDE + r;
    const float* pb = pred   + (size_t)b * IMG_STRIDE + r;
    const float4 T0 = *(const float4*)tb;
    const float4 T1 = *(const float4*)(tb + CH_STRIDE);
    const float4 P0 = *(const float4*)pb;
    const float4 P1 = *(const float4*)(pb + CH_STRIDE);

    const float f0[4] = {T0.x, T0.y, T0.z, T0.w};
    const float f1[4] = {T1.x, T1.y, T1.z, T1.w};
    const float q0[4] = {P0.x, P0.y, P0.z, P0.w};
    const float q1[4] = {P1.x, P1.y, P1.z, P1.w};

    // phase 1: cells + batched 4B LUT loads
    int   cells[4];
    float ev[4];
    float xa[4], xb[4];
    #pragma unroll
    for (int i = 0; i < 4; i++) {
        xa[i] = f0[i] * 128.f;
        xb[i] = f1[i] * 128.f;
        int ix = __float2int_rd(fmaf(xa[i], 2.f, 256.f));   // 0.5-unit cells
        int iy = __float2int_rd(fmaf(xb[i], 2.f, 256.f));
        ix = min(max(ix, 0), GRIDW - 1);
        iy = min(max(iy, 0), GRIDW - 1);
        cells[i] = (iy << 9) | ix;
    }
    #pragma unroll
    for (int i = 0; i < 4; i++) ev[i] = __ldg(&g_lut[cells[i]]);

    // phase 2: resolve + accumulate
    float acc = 0.f;
    #pragma unroll
    for (int i = 0; i < 4; i++) {
        float w;
        if (ev[i] > 0.f) {
            w = ev[i];                              // fast path (~86%)
        } else if (ev[i] >= -4.5f) {
            const float4* cd = &g_cdata[cells[i] * CAPI];
            float4 c0 = __ldg(cd + 0);              // unconditional batch,
            float4 c1 = __ldg(cd + 1);              // sentinel-padded
            float4 c2 = __ldg(cd + 2);
            float4 c3 = __ldg(cd + 3);
            float s0 = fmaf(c0.x, xa[i], fmaf(c0.y, xb[i], c0.z));
            float s1 = fmaf(c1.x, xa[i], fmaf(c1.y, xb[i], c1.z));
            float s2 = fmaf(c2.x, xa[i], fmaf(c2.y, xb[i], c2.z));
            float s3 = fmaf(c3.x, xa[i], fmaf(c3.y, xb[i], c3.z));
            float bs = s0, bw = c0.w;
            if (s1 > bs) { bs = s1; bw = c1.w; }
            if (s2 > bs) { bs = s2; bw = c2.w; }
            if (s3 > bs) { bs = s3; bw = c3.w; }
            w = bw;
        } else {                                    // pathological: full scan
            float bs = -1e30f, bw = 0.f;
            for (int k = 0; k < K_REAL; k++) {
                float4 c = __ldg(&g_ctr[k]);
                float s = fmaf(c.x, xa[i], fmaf(c.y, xb[i], c.z));
                if (s > bs) { bs = s; bw = c.w; }
            }
            w = bw;
        }

        const float d0 = q0[i] - f0[i];
        const float d1 = q1[i] - f1[i];
        acc = fmaf(fmaf(d0, d0, d1 * d1), w, acc);
    }

    // deterministic reduction: warp -> block -> fixed-point u64 atomic
    #pragma unroll
    for (int off = 16; off; off >>= 1)
        acc += __shfl_down_sync(0xFFFFFFFFu, acc, off);
    if ((t & 31) == 0) sred[t >> 5] = acc;
    __syncthreads();
    if (t < LTHREADS / 32) {
        float v = sred[t];
        #pragma unroll
        for (int off = (LTHREADS / 64); off; off >>= 1)
            v += __shfl_down_sync(0xFFu, v, off);
        if (t == 0) {
            const unsigned long long fx =
                (unsigned long long)__double2ll_rn((double)v * FIXSCALE);
            atomicAdd(&g_acc, fx);
            __threadfence();
            const unsigned ticket = atomicInc(&g_tickets, LBLOCKS - 1);
            if (ticket == LBLOCKS - 1) {
                const unsigned long long total = atomicAdd(&g_acc, 0ULL);
                out[0] = (float)((double)total * (1.0 / FIXSCALE / (double)NPIX));
                __threadfence();
                g_acc = 0ULL;                  // reset for next graph replay
            }
        }
    }
}

extern "C" void kernel_launch(void* const* d_in, const int* in_sizes, int n_in,
                              void* d_out, int out_size) {
    const float* pred    = (const float*)d_in[0];
    const float* target  = (const float*)d_in[1];
    const float* centers = (const float*)d_in[2];
    const float* cw      = (const float*)d_in[3];

    build_kernel<<<BBLOCKS, BTHREADS>>>(centers, cw);
    loss_kernel<<<LBLOCKS, LTHREADS>>>(pred, target, (float*)d_out);
}

// round 11
// speedup vs baseline: 2.0100x; 2.0100x over previous
#include <cuda_runtime.h>

// L2LossWithRebalancing — GB300 sm_103a, round 10.
// 256x256 Voronoi LUT with LINE-ENCODED float4 entries: one scattered 16B
// load resolves single-candidate cells AND the winning side of 2-candidate
// cells; the losing side costs one extra 4B load; cnt 3..8 uses padded slot
// batch; cnt>8 exact full scan. All weights exact fp32.
//   e = (A,B,C,W);  v = A*xa + B*xb + C
//   cnt==1 : (0,0, 1, w)            v>=0 -> W
//   cnt==2 : (dcx,dcy,db, w0)       v>=0 -> w0 ; v<0 -> g_w1[cell] (=w1>0)
//   cnt3-8 : (0,0,-1, 0)            g_w1[cell] = -cnt  -> slot batch
//   cnt>8  : (0,0,-1, 0)            g_w1[cell] = -1000 -> full scan

#define K_REAL 313
#define GRIDW 256
#define NCELLS (GRIDW * GRIDW)
#define CAPI 8
#define SCAP 64
#define NPIX (16 * 256 * 256)
#define CH_STRIDE 65536
#define IMG_STRIDE 131072
#define LTHREADS 256
#define PXT 4
#define LBLOCKS (NPIX / (LTHREADS * PXT))   // 1024
#define BTHREADS 256
#define BBLOCKS 256                         // one block per 16x16 supercell
#define FIXSCALE 1048576.0                  // 2^20

__device__ float4             g_lut[NCELLS];            // line-encoded entries
__device__ float              g_w1[NCELLS];             // 2nd weight / tag
__device__ float4             g_cdata[NCELLS * CAPI];   // slots for cnt 3..8
__device__ float4             g_ctr[K_REAL];            // (2ca,2cb,-|c|^2,w)
__device__ unsigned long long g_acc;                    // zero-init; self-reset
__device__ unsigned int       g_tickets;                // zero-init; wraps

// ---------------------------------------------------------------------------
// Build: block = 16x16-cell supercell, thread = cell.
// ---------------------------------------------------------------------------
__global__ __launch_bounds__(BTHREADS)
void build_kernel(const float* __restrict__ centers,
                  const float* __restrict__ cw) {
    __shared__ float4 sB[K_REAL];
    __shared__ float4 scand[SCAP];
    __shared__ float  swarp[BTHREADS / 32];
    __shared__ float  s_sth;
    __shared__ int    s_cnt;

    const int t = threadIdx.x;
    for (int i = t; i < K_REAL; i += BTHREADS) {
        float ca = centers[2 * i];
        float cb = centers[2 * i + 1];
        float4 v = make_float4(2.f * ca, 2.f * cb,
                               -(ca * ca + cb * cb), cw[i]);
        sB[i] = v;
        if (blockIdx.x == 0) g_ctr[i] = v;
    }
    __syncthreads();

    const int sx = blockIdx.x & 15;
    const int sy = blockIdx.x >> 4;
    const float sccx = 16.f * sx - 120.f;
    const float sccy = 16.f * sy - 120.f;
    const float scc2 = sccx * sccx + sccy * sccy;

    float m = -1e30f;
    for (int i = t; i < K_REAL; i += BTHREADS) {
        float4 c = sB[i];
        m = fmaxf(m, fmaf(c.x, sccx, fmaf(c.y, sccy, c.z)));
    }
    #pragma unroll
    for (int off = 16; off; off >>= 1)
        m = fmaxf(m, __shfl_xor_sync(0xFFFFFFFFu, m, off));
    if ((t & 31) == 0) swarp[t >> 5] = m;
    __syncthreads();
    if (t == 0) {
        float mm = swarp[0];
        #pragma unroll
        for (int wnum = 1; wnum < BTHREADS / 32; wnum++)
            mm = fmaxf(mm, swarp[wnum]);
        float d2min = fmaxf(scc2 - mm, 0.f);
        float T = sqrtf(d2min) + 22.75f;   // 2*7.5*sqrt2 + sqrt2 + margin
        s_sth = scc2 - T * T;
    }
    __syncthreads();

    // deterministic candidate compaction: warp 0, index-ordered
    if (t < 32) {
        const float sth_sc = s_sth;
        int cnt = 0;
        for (int base = 0; base < K_REAL; base += 32) {
            const int i = base + t;
            bool pred = false;
            float4 c = make_float4(0.f, 0.f, 0.f, 0.f);
            if (i < K_REAL) {
                c = sB[i];
                pred = (fmaf(c.x, sccx, fmaf(c.y, sccy, c.z)) >= sth_sc);
            }
            const unsigned mask = __ballot_sync(0xFFFFFFFFu, pred);
            if (pred) {
                const int pos = cnt + __popc(mask & ((1u << t) - 1u));
                if (pos < SCAP) scand[pos] = c;
            }
            cnt += __popc(mask);
        }
        if (t == 0) s_cnt = cnt;
    }
    __syncthreads();

    const float4* list;
    int n;
    if (s_cnt <= SCAP) { list = scand; n = s_cnt; }
    else               { list = sB;    n = K_REAL; }   // overflow fallback

    const int ix = 16 * sx + (t & 15);
    const int iy = 16 * sy + (t >> 4);
    const float ccx = (float)ix - 127.5f;
    const float ccy = (float)iy - 127.5f;
    const float cc2 = ccx * ccx + ccy * ccy;

    float smax = -1e30f;
    for (int k = 0; k < n; k++) {
        float4 c = list[k];
        smax = fmaxf(smax, fmaf(c.x, ccx, fmaf(c.y, ccy, c.z)));
    }
    float d2min = fmaxf(cc2 - smax, 0.f);
    float T = sqrtf(d2min) + 1.43421356f;  // sqrt(2) diag + fp margin
    const float sth = cc2 - T * T;

    const int cell = (iy << 8) | ix;
    int cnt = 0;
    float4 cand0, cand1;
    float4* slot = &g_cdata[cell * CAPI];
    for (int k = 0; k < n; k++) {
        float4 c = list[k];
        float s = fmaf(c.x, ccx, fmaf(c.y, ccy, c.z));
        if (s >= sth) {
            if (cnt == 0) cand0 = c;
            else if (cnt == 1) cand1 = c;
            if (cnt < CAPI) slot[cnt] = c;
            cnt++;
        }
    }
    float4 e;
    float w1v = 0.f;
    bool write_w1 = true;
    if (cnt == 1) {
        e = make_float4(0.f, 0.f, 1.f, cand0.w);
        write_w1 = false;
    } else if (cnt == 2) {
        // v = s0 - s1; v>=0 -> cand0 (lower index, matches argmin ties)
        e = make_float4(cand0.x - cand1.x, cand0.y - cand1.y,
                        cand0.z - cand1.z, cand0.w);
        w1v = cand1.w;                         // positive
    } else if (cnt <= CAPI) {
        const float4 sentinel = make_float4(0.f, 0.f, -1e30f, 0.f);
        for (int j = cnt; j < CAPI; j++) slot[j] = sentinel;
        e = make_float4(0.f, 0.f, -1.f, 0.f);
        w1v = -(float)cnt;                     // tag: slot batch
    } else {
        e = make_float4(0.f, 0.f, -1.f, 0.f);
        w1v = -1000.f;                         // tag: full scan
    }
    g_lut[cell] = e;
    if (write_w1) g_w1[cell] = w1v;
}

// ---------------------------------------------------------------------------
// Loss: 4 pixels/thread; one scattered 16B load resolves ~94% of pixels.
// ---------------------------------------------------------------------------
__global__ __launch_bounds__(LTHREADS)
void loss_kernel(const float* __restrict__ pred,
                 const float* __restrict__ target,
                 float* __restrict__ out) {
    __shared__ float sred[LTHREADS / 32];

    const int t   = threadIdx.x;
    const int tid = blockIdx.x * LTHREADS + t;
    const int p   = tid * PXT;
    const int b   = p >> 16;
    const int r   = p & 65535;

    const float* tb = target + (size_t)b * IMG_STRIDE + r;
    const float* pb = pred   + (size_t)b * IMG_STRIDE + r;
    const float4 T0 = *(const float4*)tb;
    const float4 T1 = *(const float4*)(tb + CH_STRIDE);
    const float4 P0 = *(const float4*)pb;
    const float4 P1 = *(const float4*)(pb + CH_STRIDE);

    const float f0[4] = {T0.x, T0.y, T0.z, T0.w};
    const float f1[4] = {T1.x, T1.y, T1.z, T1.w};
    const float q0[4] = {P0.x, P0.y, P0.z, P0.w};
    const float q1[4] = {P1.x, P1.y, P1.z, P1.w};

    // phase 1: cells + batched LUT loads (MLP)
    int    cells[4];
    float4 e[4];
    float  xa[4], xb[4];
    #pragma unroll
    for (int i = 0; i < 4; i++) {
        xa[i] = f0[i] * 128.f;
        xb[i] = f1[i] * 128.f;
        int ix = __float2int_rd(xa[i] + 128.f);
        int iy = __float2int_rd(xb[i] + 128.f);
        ix = min(max(ix, 0), GRIDW - 1);
        iy = min(max(iy, 0), GRIDW - 1);
        cells[i] = (iy << 8) | ix;
    }
    #pragma unroll
    for (int i = 0; i < 4; i++) e[i] = __ldg(&g_lut[cells[i]]);

    // phase 2: resolve + accumulate
    float acc = 0.f;
    #pragma unroll
    for (int i = 0; i < 4; i++) {
        const float v = fmaf(e[i].x, xa[i], fmaf(e[i].y, xb[i], e[i].z));
        float w;
        if (v >= 0.f) {
            w = e[i].w;                           // single-cand or 2-cand win
        } else {
            const float w1v = __ldg(&g_w1[cells[i]]);
            if (w1v > 0.f) {
                w = w1v;                          // 2-cand, other side
            } else if (w1v > -500.f) {            // cnt 3..8: padded slots
                const float4* cd = &g_cdata[cells[i] * CAPI];
                float4 c0 = __ldg(cd + 0);
                float4 c1 = __ldg(cd + 1);
                float4 c2 = __ldg(cd + 2);
                float4 c3 = __ldg(cd + 3);
                float4 c4 = __ldg(cd + 4);
                float4 c5 = __ldg(cd + 5);
                float4 c6 = __ldg(cd + 6);
                float4 c7 = __ldg(cd + 7);
                float s0 = fmaf(c0.x, xa[i], fmaf(c0.y, xb[i], c0.z));
                float s1 = fmaf(c1.x, xa[i], fmaf(c1.y, xb[i], c1.z));
                float s2 = fmaf(c2.x, xa[i], fmaf(c2.y, xb[i], c2.z));
                float s3 = fmaf(c3.x, xa[i], fmaf(c3.y, xb[i], c3.z));
                float s4 = fmaf(c4.x, xa[i], fmaf(c4.y, xb[i], c4.z));
                float s5 = fmaf(c5.x, xa[i], fmaf(c5.y, xb[i], c5.z));
                float s6 = fmaf(c6.x, xa[i], fmaf(c6.y, xb[i], c6.z));
                float s7 = fmaf(c7.x, xa[i], fmaf(c7.y, xb[i], c7.z));
                float bs = s0, bw = c0.w;
                if (s1 > bs) { bs = s1; bw = c1.w; }
                if (s2 > bs) { bs = s2; bw = c2.w; }
                if (s3 > bs) { bs = s3; bw = c3.w; }
                if (s4 > bs) { bs = s4; bw = c4.w; }
                if (s5 > bs) { bs = s5; bw = c5.w; }
                if (s6 > bs) { bs = s6; bw = c6.w; }
                if (s7 > bs) { bs = s7; bw = c7.w; }
                w = bw;
            } else {                              // pathological: full scan
                float bs = -1e30f, bw = 0.f;
                for (int k = 0; k < K_REAL; k++) {
                    float4 c = __ldg(&g_ctr[k]);
                    float s = fmaf(c.x, xa[i], fmaf(c.y, xb[i], c.z));
                    if (s > bs) { bs = s; bw = c.w; }
                }
                w = bw;
            }
        }

        const float d0 = q0[i] - f0[i];
        const float d1 = q1[i] - f1[i];
        acc = fmaf(fmaf(d0, d0, d1 * d1), w, acc);
    }

    // deterministic reduction: warp -> block -> fixed-point u64 atomic
    #pragma unroll
    for (int off = 16; off; off >>= 1)
        acc += __shfl_down_sync(0xFFFFFFFFu, acc, off);
    if ((t & 31) == 0) sred[t >> 5] = acc;
    __syncthreads();
    if (t < LTHREADS / 32) {
        float v = sred[t];
        #pragma unroll
        for (int off = (LTHREADS / 64); off; off >>= 1)
            v += __shfl_down_sync(0xFFu, v, off);
        if (t == 0) {
            const unsigned long long fx =
                (unsigned long long)__double2ll_rn((double)v * FIXSCALE);
            atomicAdd(&g_acc, fx);
            __threadfence();
            const unsigned ticket = atomicInc(&g_tickets, LBLOCKS - 1);
            if (ticket == LBLOCKS - 1) {
                const unsigned long long total = atomicAdd(&g_acc, 0ULL);
                out[0] = (float)((double)total * (1.0 / FIXSCALE / (double)NPIX));
                __threadfence();
                g_acc = 0ULL;                  // reset for next graph replay
            }
        }
    }
}

extern "C" void kernel_launch(void* const* d_in, const int* in_sizes, int n_in,
                              void* d_out, int out_size) {
    const float* pred    = (const float*)d_in[0];
    const float* target  = (const float*)d_in[1];
    const float* centers = (const float*)d_in[2];
    const float* cw      = (const float*)d_in[3];

    build_kernel<<<BBLOCKS, BTHREADS>>>(centers, cw);
    loss_kernel<<<LBLOCKS, LTHREADS>>>(pred, target, (float*)d_out);
}

// round 12
// speedup vs baseline: 2.0485x; 1.0192x over previous
#include <cuda_runtime.h>

// L2LossWithRebalancing — GB300 sm_103a, round 12.
// SMEM-resident Voronoi LUT: the full 256x256 cell->center-index table (u16,
// 128KB) lives in shared memory of a persistent 148-block kernel. Scattered
// per-pixel lookups become ~29-cycle LDS instead of queued L2 round trips.
//   idx < 0x8000 : single candidate, weight = swtab[idx] (exact fp32)
//   0x8000|cnt   : cnt in [2,8] sentinel-padded slots in g_cdata (global)
//   0xFFFF       : pathological cell -> exact full scan of g_ctr
// Deterministic fixed-point u64 atomic reduction, graph-replay safe.

#define K_REAL 313
#define GRIDW 256
#define NCELLS (GRIDW * GRIDW)
#define CAPI 8
#define SCAP 64
#define NPIX (16 * 256 * 256)
#define NQUAD (NPIX / 4)
#define CH_STRIDE 65536
#define IMG_STRIDE 131072
#define LTHREADS 512
#define LBLOCKS 148                         // persistent: one block per SM
#define BTHREADS 256
#define BBLOCKS 256                         // one block per 16x16 supercell
#define FIXSCALE 1048576.0                  // 2^20

// dynamic smem layout: u16 lut[NCELLS] | float wtab[320]
#define SMEM_BYTES (NCELLS * 2 + 320 * 4)

__device__ unsigned short     g_cellidx[NCELLS];
__device__ float              g_wtab[K_REAL];
__device__ float4             g_cdata[NCELLS * CAPI];   // slots for cnt 2..8
__device__ float4             g_ctr[K_REAL];            // (2ca,2cb,-|c|^2,w)
__device__ unsigned long long g_acc;                    // zero-init; self-reset
__device__ unsigned int       g_tickets;                // zero-init; wraps

// ---------------------------------------------------------------------------
// Build: block = 16x16-cell supercell, thread = cell.
// score s_k(x) = 2*c_k.x - |c_k|^2 ; argmin dist == argmax score.
// ---------------------------------------------------------------------------
__global__ __launch_bounds__(BTHREADS)
void build_kernel(const float* __restrict__ centers,
                  const float* __restrict__ cw) {
    __shared__ float4         sB[K_REAL];
    __shared__ float4         scand[SCAP];
    __shared__ unsigned short scidx[SCAP];
    __shared__ float          swarp[BTHREADS / 32];
    __shared__ float          s_sth;
    __shared__ int            s_cnt;

    const int t = threadIdx.x;
    for (int i = t; i < K_REAL; i += BTHREADS) {
        float ca = centers[2 * i];
        float cb = centers[2 * i + 1];
        float4 v = make_float4(2.f * ca, 2.f * cb,
                               -(ca * ca + cb * cb), cw[i]);
        sB[i] = v;
        if (blockIdx.x == 0) { g_ctr[i] = v; g_wtab[i] = cw[i]; }
    }
    __syncthreads();

    const int sx = blockIdx.x & 15;
    const int sy = blockIdx.x >> 4;
    const float sccx = 16.f * sx - 120.f;
    const float sccy = 16.f * sy - 120.f;
    const float scc2 = sccx * sccx + sccy * sccy;

    float m = -1e30f;
    for (int i = t; i < K_REAL; i += BTHREADS) {
        float4 c = sB[i];
        m = fmaxf(m, fmaf(c.x, sccx, fmaf(c.y, sccy, c.z)));
    }
    #pragma unroll
    for (int off = 16; off; off >>= 1)
        m = fmaxf(m, __shfl_xor_sync(0xFFFFFFFFu, m, off));
    if ((t & 31) == 0) swarp[t >> 5] = m;
    __syncthreads();
    if (t == 0) {
        float mm = swarp[0];
        #pragma unroll
        for (int wnum = 1; wnum < BTHREADS / 32; wnum++)
            mm = fmaxf(mm, swarp[wnum]);
        float d2min = fmaxf(scc2 - mm, 0.f);
        float T = sqrtf(d2min) + 22.75f;   // 2*7.5*sqrt2 + sqrt2 + margin
        s_sth = scc2 - T * T;
    }
    __syncthreads();

    // deterministic candidate compaction (warp 0, index-ordered, with indices)
    if (t < 32) {
        const float sth_sc = s_sth;
        int cnt = 0;
        for (int base = 0; base < K_REAL; base += 32) {
            const int i = base + t;
            bool pred = false;
            float4 c = make_float4(0.f, 0.f, 0.f, 0.f);
            if (i < K_REAL) {
                c = sB[i];
                pred = (fmaf(c.x, sccx, fmaf(c.y, sccy, c.z)) >= sth_sc);
            }
            const unsigned mask = __ballot_sync(0xFFFFFFFFu, pred);
            if (pred) {
                const int pos = cnt + __popc(mask & ((1u << t) - 1u));
                if (pos < SCAP) { scand[pos] = c; scidx[pos] = (unsigned short)i; }
            }
            cnt += __popc(mask);
        }
        if (t == 0) s_cnt = cnt;
    }
    __syncthreads();

    const bool use_full = (s_cnt > SCAP);
    const int n = use_full ? K_REAL : s_cnt;

    const int ix = 16 * sx + (t & 15);
    const int iy = 16 * sy + (t >> 4);
    const float ccx = (float)ix - 127.5f;
    const float ccy = (float)iy - 127.5f;
    const float cc2 = ccx * ccx + ccy * ccy;

    float smax = -1e30f;
    for (int k = 0; k < n; k++) {
        float4 c = use_full ? sB[k] : scand[k];
        smax = fmaxf(smax, fmaf(c.x, ccx, fmaf(c.y, ccy, c.z)));
    }
    float d2min = fmaxf(cc2 - smax, 0.f);
    float T = sqrtf(d2min) + 1.43421356f;  // sqrt(2) diag + fp margin
    const float sth = cc2 - T * T;

    const int cell = (iy << 8) | ix;
    int cnt = 0;
    unsigned short ci0 = 0;
    float4* slot = &g_cdata[cell * CAPI];
    for (int k = 0; k < n; k++) {
        float4 c = use_full ? sB[k] : scand[k];
        float s = fmaf(c.x, ccx, fmaf(c.y, ccy, c.z));
        if (s >= sth) {
            if (cnt == 0) ci0 = use_full ? (unsigned short)k : scidx[k];
            if (cnt < CAPI) slot[cnt] = c;
            cnt++;
        }
    }
    unsigned short tag;
    if (cnt == 1) {
        tag = ci0;                                 // direct center index
    } else if (cnt <= CAPI) {
        const float4 sentinel = make_float4(0.f, 0.f, -1e30f, 0.f);
        for (int j = cnt; j < CAPI; j++) slot[j] = sentinel;
        tag = (unsigned short)(0x8000u | (unsigned)cnt);
    } else {
        tag = 0xFFFFu;                             // full-scan fallback
    }
    g_cellidx[cell] = tag;
}

// ---------------------------------------------------------------------------
// Loss: persistent blocks, SMEM-resident LUT, grid-stride over pixel quads.
// ---------------------------------------------------------------------------
__global__ __launch_bounds__(LTHREADS)
void loss_kernel(const float* __restrict__ pred,
                 const float* __restrict__ target,
                 float* __restrict__ out) {
    extern __shared__ unsigned char smem_raw[];
    unsigned short* slut = (unsigned short*)smem_raw;            // 128KB
    float*          swtab = (float*)(smem_raw + NCELLS * 2);     // 313 floats
    __shared__ float sred[LTHREADS / 32];

    const int t = threadIdx.x;

    // cooperative SMEM fill: LUT via uint4 (coalesced), weight table
    {
        const uint4* src = (const uint4*)g_cellidx;
        uint4* dst = (uint4*)slut;
        for (int i = t; i < NCELLS * 2 / 16; i += LTHREADS) dst[i] = src[i];
        for (int i = t; i < K_REAL; i += LTHREADS) swtab[i] = g_wtab[i];
    }
    __syncthreads();

    float acc = 0.f;
    const int stride = LBLOCKS * LTHREADS;
    for (int q = blockIdx.x * LTHREADS + t; q < NQUAD; q += stride) {
        const int p = q << 2;
        const int b = p >> 16;
        const int r = p & 65535;

        const float* tb = target + (size_t)b * IMG_STRIDE + r;
        const float* pb = pred   + (size_t)b * IMG_STRIDE + r;
        const float4 T0 = *(const float4*)tb;
        const float4 T1 = *(const float4*)(tb + CH_STRIDE);
        const float4 P0 = *(const float4*)pb;
        const float4 P1 = *(const float4*)(pb + CH_STRIDE);

        const float f0[4] = {T0.x, T0.y, T0.z, T0.w};
        const float f1[4] = {T1.x, T1.y, T1.z, T1.w};
        const float q0[4] = {P0.x, P0.y, P0.z, P0.w};
        const float q1[4] = {P1.x, P1.y, P1.z, P1.w};

        #pragma unroll
        for (int i = 0; i < 4; i++) {
            const float xa = f0[i] * 128.f;
            const float xb = f1[i] * 128.f;
            int ix = __float2int_rd(xa + 128.f);
            int iy = __float2int_rd(xb + 128.f);
            ix = min(max(ix, 0), GRIDW - 1);
            iy = min(max(iy, 0), GRIDW - 1);
            const int cell = (iy << 8) | ix;
            const unsigned idx = slut[cell];

            float w;
            if (idx < 0x8000u) {
                w = swtab[idx];                       // fast path, all-SMEM
            } else if (idx != 0xFFFFu) {
                const unsigned cnt = idx & 0xFFu;     // 2..8
                const float4* cd = &g_cdata[cell * CAPI];
                float4 c0 = __ldg(cd + 0);
                float4 c1 = __ldg(cd + 1);
                float4 c2 = __ldg(cd + 2);
                float4 c3 = __ldg(cd + 3);
                float s0 = fmaf(c0.x, xa, fmaf(c0.y, xb, c0.z));
                float s1 = fmaf(c1.x, xa, fmaf(c1.y, xb, c1.z));
                float s2 = fmaf(c2.x, xa, fmaf(c2.y, xb, c2.z));
                float s3 = fmaf(c3.x, xa, fmaf(c3.y, xb, c3.z));
                float bs = s0, bw = c0.w;
                if (s1 > bs) { bs = s1; bw = c1.w; }
                if (s2 > bs) { bs = s2; bw = c2.w; }
                if (s3 > bs) { bs = s3; bw = c3.w; }
                if (cnt > 4u) {
                    float4 c4 = __ldg(cd + 4);
                    float4 c5 = __ldg(cd + 5);
                    float4 c6 = __ldg(cd + 6);
                    float4 c7 = __ldg(cd + 7);
                    float s4 = fmaf(c4.x, xa, fmaf(c4.y, xb, c4.z));
                    float s5 = fmaf(c5.x, xa, fmaf(c5.y, xb, c5.z));
                    float s6 = fmaf(c6.x, xa, fmaf(c6.y, xb, c6.z));
                    float s7 = fmaf(c7.x, xa, fmaf(c7.y, xb, c7.z));
                    if (s4 > bs) { bs = s4; bw = c4.w; }
                    if (s5 > bs) { bs = s5; bw = c5.w; }
                    if (s6 > bs) { bs = s6; bw = c6.w; }
                    if (s7 > bs) { bs = s7; bw = c7.w; }
                }
                w = bw;
            } else {                                  // pathological: full scan
                float bs = -1e30f, bw = 0.f;
                for (int k = 0; k < K_REAL; k++) {
                    float4 c = __ldg(&g_ctr[k]);
                    float s = fmaf(c.x, xa, fmaf(c.y, xb, c.z));
                    if (s > bs) { bs = s; bw = c.w; }
                }
                w = bw;
            }

            const float d0 = q0[i] - f0[i];
            const float d1 = q1[i] - f1[i];
            acc = fmaf(fmaf(d0, d0, d1 * d1), w, acc);
        }
    }

    // deterministic reduction: warp -> block -> fixed-point u64 atomic
    #pragma unroll
    for (int off = 16; off; off >>= 1)
        acc += __shfl_down_sync(0xFFFFFFFFu, acc, off);
    if ((t & 31) == 0) sred[t >> 5] = acc;
    __syncthreads();
    if (t < LTHREADS / 32) {
        float v = sred[t];
        #pragma unroll
        for (int off = (LTHREADS / 64); off; off >>= 1)
            v += __shfl_down_sync(0xFFFFu, v, off);
        if (t == 0) {
            const unsigned long long fx =
                (unsigned long long)__double2ll_rn((double)v * FIXSCALE);
            atomicAdd(&g_acc, fx);
            __threadfence();
            const unsigned ticket = atomicInc(&g_tickets, LBLOCKS - 1);
            if (ticket == LBLOCKS - 1) {
                const unsigned long long total = atomicAdd(&g_acc, 0ULL);
                out[0] = (float)((double)total * (1.0 / FIXSCALE / (double)NPIX));
                __threadfence();
                g_acc = 0ULL;                  // reset for next graph replay
            }
        }
    }
}

extern "C" void kernel_launch(void* const* d_in, const int* in_sizes, int n_in,
                              void* d_out, int out_size) {
    const float* pred    = (const float*)d_in[0];
    const float* target  = (const float*)d_in[1];
    const float* centers = (const float*)d_in[2];
    const float* cw      = (const float*)d_in[3];

    cudaFuncSetAttribute(loss_kernel,
                         cudaFuncAttributeMaxDynamicSharedMemorySize,
                         SMEM_BYTES);

    build_kernel<<<BBLOCKS, BTHREADS>>>(centers, cw);
    loss_kernel<<<LBLOCKS, LTHREADS, SMEM_BYTES>>>(pred, target, (float*)d_out);
}

// round 13
// speedup vs baseline: 2.2309x; 1.0890x over previous
#include <cuda_runtime.h>

// L2LossWithRebalancing — GB300 sm_103a, round 13.
// Tail-elimination round: no path ever does a serial 313-load scan.
//   cnt==1  : weight inline in 8B LUT entry (one load)
//   cnt 2-16: sentinel-padded slots, batches of 4 with early exit
//   cnt>16  : per-supercell candidate list (<=64, batched 4-wide scan)
//   supercell overflow: batched 4-wide scan of all 313 centers (never serial)
// Deterministic fixed-point u64 atomic reduction, graph-replay safe.

#define K_REAL 313
#define GRIDW 256
#define NCELLS (GRIDW * GRIDW)
#define CAPI 16
#define SCAP 64
#define NPIX (16 * 256 * 256)
#define CH_STRIDE 65536
#define IMG_STRIDE 131072
#define LTHREADS 256
#define PXT 4
#define LBLOCKS (NPIX / (LTHREADS * PXT))   // 1024
#define BTHREADS 256
#define BBLOCKS 256                         // one block per 16x16 supercell
#define FIXSCALE 1048576.0                  // 2^20

__device__ uint2              g_lut[NCELLS];
__device__ float4             g_cdata[NCELLS * CAPI];   // slots for cnt 2..16
__device__ float4             g_slist[BBLOCKS * SCAP];  // per-supercell lists
__device__ int                g_slen[BBLOCKS];
__device__ float4             g_ctr[K_REAL];            // (2ca,2cb,-|c|^2,w)
__device__ unsigned long long g_acc;                    // zero-init; self-reset
__device__ unsigned int       g_tickets;                // zero-init; wraps

// ---------------------------------------------------------------------------
// Build: block = 16x16-cell supercell, thread = cell.
// score s_k(x) = 2*c_k.x - |c_k|^2 ; argmin dist == argmax score.
// ---------------------------------------------------------------------------
__global__ __launch_bounds__(BTHREADS)
void build_kernel(const float* __restrict__ centers,
                  const float* __restrict__ cw) {
    __shared__ float4 sB[K_REAL];
    __shared__ float4 scand[SCAP];
    __shared__ float  swarp[BTHREADS / 32];
    __shared__ float  s_sth;
    __shared__ int    s_cnt;

    const int t = threadIdx.x;
    for (int i = t; i < K_REAL; i += BTHREADS) {
        float ca = centers[2 * i];
        float cb = centers[2 * i + 1];
        float4 v = make_float4(2.f * ca, 2.f * cb,
                               -(ca * ca + cb * cb), cw[i]);
        sB[i] = v;
        if (blockIdx.x == 0) g_ctr[i] = v;
    }
    __syncthreads();

    const int sx = blockIdx.x & 15;
    const int sy = blockIdx.x >> 4;
    const float sccx = 16.f * sx - 120.f;
    const float sccy = 16.f * sy - 120.f;
    const float scc2 = sccx * sccx + sccy * sccy;

    float m = -1e30f;
    for (int i = t; i < K_REAL; i += BTHREADS) {
        float4 c = sB[i];
        m = fmaxf(m, fmaf(c.x, sccx, fmaf(c.y, sccy, c.z)));
    }
    #pragma unroll
    for (int off = 16; off; off >>= 1)
        m = fmaxf(m, __shfl_xor_sync(0xFFFFFFFFu, m, off));
    if ((t & 31) == 0) swarp[t >> 5] = m;
    __syncthreads();
    if (t == 0) {
        float mm = swarp[0];
        #pragma unroll
        for (int wnum = 1; wnum < BTHREADS / 32; wnum++)
            mm = fmaxf(mm, swarp[wnum]);
        float d2min = fmaxf(scc2 - mm, 0.f);
        float T = sqrtf(d2min) + 22.75f;   // 2*7.5*sqrt2 + sqrt2 + margin
        s_sth = scc2 - T * T;
    }
    __syncthreads();

    // deterministic candidate compaction: warp 0, index-ordered
    if (t < 32) {
        const float sth_sc = s_sth;
        int cnt = 0;
        for (int base = 0; base < K_REAL; base += 32) {
            const int i = base + t;
            bool pred = false;
            float4 c = make_float4(0.f, 0.f, 0.f, 0.f);
            if (i < K_REAL) {
                c = sB[i];
                pred = (fmaf(c.x, sccx, fmaf(c.y, sccy, c.z)) >= sth_sc);
            }
            const unsigned mask = __ballot_sync(0xFFFFFFFFu, pred);
            if (pred) {
                const int pos = cnt + __popc(mask & ((1u << t) - 1u));
                if (pos < SCAP) scand[pos] = c;
            }
            cnt += __popc(mask);
        }
        if (t == 0) s_cnt = cnt;
    }
    __syncthreads();

    const bool use_full = (s_cnt > SCAP);
    const int n = use_full ? K_REAL : s_cnt;

    // persist supercell list for the loss kernel's worst-case path
    if (!use_full) {
        for (int i = t; i < s_cnt; i += BTHREADS)
            g_slist[blockIdx.x * SCAP + i] = scand[i];
        if (t == 0) g_slen[blockIdx.x] = s_cnt;
    } else {
        if (t == 0) g_slen[blockIdx.x] = 0x7FFFFFFF;   // scan g_ctr instead
    }

    const int ix = 16 * sx + (t & 15);
    const int iy = 16 * sy + (t >> 4);
    const float ccx = (float)ix - 127.5f;
    const float ccy = (float)iy - 127.5f;
    const float cc2 = ccx * ccx + ccy * ccy;

    float smax = -1e30f;
    for (int k = 0; k < n; k++) {
        float4 c = use_full ? sB[k] : scand[k];
        smax = fmaxf(smax, fmaf(c.x, ccx, fmaf(c.y, ccy, c.z)));
    }
    float d2min = fmaxf(cc2 - smax, 0.f);
    float T = sqrtf(d2min) + 1.43421356f;  // sqrt(2) diag + fp margin
    const float sth = cc2 - T * T;

    const int cell = (iy << 8) | ix;
    int cnt = 0;
    float w0 = 0.f;
    float4* slot = &g_cdata[cell * CAPI];
    for (int k = 0; k < n; k++) {
        float4 c = use_full ? sB[k] : scand[k];
        float s = fmaf(c.x, ccx, fmaf(c.y, ccy, c.z));
        if (s >= sth) {
            if (cnt == 0) w0 = c.w;
            if (cnt < CAPI) slot[cnt] = c;
            cnt++;
        }
    }
    uint2 e;
    if (cnt == 1) {
        e.x = __float_as_uint(w0); e.y = 1u;
    } else if (cnt <= CAPI) {
        // pad only to the next multiple of 4 (loss reads whole batches)
        const int pad = (cnt + 3) & ~3;
        const float4 sentinel = make_float4(0.f, 0.f, -1e30f, 0.f);
        for (int j = cnt; j < pad; j++) slot[j] = sentinel;
        e.x = 0u; e.y = (unsigned)cnt;
    } else {
        e.x = 0u; e.y = 0xFFFFu;               // supercell-list scan
    }
    g_lut[cell] = e;
}

// ---------------------------------------------------------------------------
// Loss: 4 pixels/thread, phase-split; every path uses batched (MLP) loads.
// ---------------------------------------------------------------------------
__device__ __forceinline__ void eval4(const float4* cd, float xa, float xb,
                                      float& bs, float& bw) {
    float4 c0 = __ldg(cd + 0);
    float4 c1 = __ldg(cd + 1);
    float4 c2 = __ldg(cd + 2);
    float4 c3 = __ldg(cd + 3);
    float s0 = fmaf(c0.x, xa, fmaf(c0.y, xb, c0.z));
    float s1 = fmaf(c1.x, xa, fmaf(c1.y, xb, c1.z));
    float s2 = fmaf(c2.x, xa, fmaf(c2.y, xb, c2.z));
    float s3 = fmaf(c3.x, xa, fmaf(c3.y, xb, c3.z));
    if (s0 > bs) { bs = s0; bw = c0.w; }
    if (s1 > bs) { bs = s1; bw = c1.w; }
    if (s2 > bs) { bs = s2; bw = c2.w; }
    if (s3 > bs) { bs = s3; bw = c3.w; }
}

__global__ __launch_bounds__(LTHREADS)
void loss_kernel(const float* __restrict__ pred,
                 const float* __restrict__ target,
                 float* __restrict__ out) {
    __shared__ float sred[LTHREADS / 32];

    const int t   = threadIdx.x;
    const int tid = blockIdx.x * LTHREADS + t;
    const int p   = tid * PXT;
    const int b   = p >> 16;
    const int r   = p & 65535;

    const float* tb = target + (size_t)b * IMG_STRIDE + r;
    const float* pb = pred   + (size_t)b * IMG_STRIDE + r;
    const float4 T0 = *(const float4*)tb;
    const float4 T1 = *(const float4*)(tb + CH_STRIDE);
    const float4 P0 = *(const float4*)pb;
    const float4 P1 = *(const float4*)(pb + CH_STRIDE);

    const float f0[4] = {T0.x, T0.y, T0.z, T0.w};
    const float f1[4] = {T1.x, T1.y, T1.z, T1.w};
    const float q0[4] = {P0.x, P0.y, P0.z, P0.w};
    const float q1[4] = {P1.x, P1.y, P1.z, P1.w};

    // phase 1: cells + batched LUT loads
    int   cells[4];
    uint2 es[4];
    float xa[4], xb[4];
    #pragma unroll
    for (int i = 0; i < 4; i++) {
        xa[i] = f0[i] * 128.f;
        xb[i] = f1[i] * 128.f;
        int ix = __float2int_rd(xa[i] + 128.f);
        int iy = __float2int_rd(xb[i] + 128.f);
        ix = min(max(ix, 0), GRIDW - 1);
        iy = min(max(iy, 0), GRIDW - 1);
        cells[i] = (iy << 8) | ix;
    }
    #pragma unroll
    for (int i = 0; i < 4; i++) es[i] = __ldg(&g_lut[cells[i]]);

    // phase 2: resolve + accumulate
    float acc = 0.f;
    #pragma unroll
    for (int i = 0; i < 4; i++) {
        const unsigned cnt = es[i].y;
        float w;
        if (cnt == 1u) {
            w = __uint_as_float(es[i].x);           // fast path
        } else if (cnt <= (unsigned)CAPI) {
            const float4* cd = &g_cdata[cells[i] * CAPI];
            float bs = -1e30f, bw = 0.f;
            eval4(cd, xa[i], xb[i], bs, bw);
            if (cnt > 4u) {
                eval4(cd + 4, xa[i], xb[i], bs, bw);
                if (cnt > 8u) {
                    eval4(cd + 8, xa[i], xb[i], bs, bw);
                    if (cnt > 12u) eval4(cd + 12, xa[i], xb[i], bs, bw);
                }
            }
            w = bw;
        } else {
            // worst case: batched scan of supercell list (or all centers)
            const int sc = ((cells[i] >> 12) << 4) | ((cells[i] & 255) >> 4);
            int n = __ldg(&g_slen[sc]);
            const float4* ls;
            if (n <= SCAP) { ls = &g_slist[sc * SCAP]; }
            else           { ls = g_ctr; n = K_REAL; }
            float bs = -1e30f, bw = 0.f;
            for (int k = 0; k < n; k += 4) {
                // index-clamped 4-wide batch (duplicates don't change max)
                const int k1 = min(k + 1, n - 1);
                const int k2 = min(k + 2, n - 1);
                const int k3 = min(k + 3, n - 1);
                float4 c0 = __ldg(ls + k);
                float4 c1 = __ldg(ls + k1);
                float4 c2 = __ldg(ls + k2);
                float4 c3 = __ldg(ls + k3);
                float s0 = fmaf(c0.x, xa[i], fmaf(c0.y, xb[i], c0.z));
                float s1 = fmaf(c1.x, xa[i], fmaf(c1.y, xb[i], c1.z));
                float s2 = fmaf(c2.x, xa[i], fmaf(c2.y, xb[i], c2.z));
                float s3 = fmaf(c3.x, xa[i], fmaf(c3.y, xb[i], c3.z));
                if (s0 > bs) { bs = s0; bw = c0.w; }
                if (s1 > bs) { bs = s1; bw = c1.w; }
                if (s2 > bs) { bs = s2; bw = c2.w; }
                if (s3 > bs) { bs = s3; bw = c3.w; }
            }
            w = bw;
        }

        const float d0 = q0[i] - f0[i];
        const float d1 = q1[i] - f1[i];
        acc = fmaf(fmaf(d0, d0, d1 * d1), w, acc);
    }

    // deterministic reduction: warp -> block -> fixed-point u64 atomic
    #pragma unroll
    for (int off = 16; off; off >>= 1)
        acc += __shfl_down_sync(0xFFFFFFFFu, acc, off);
    if ((t & 31) == 0) sred[t >> 5] = acc;
    __syncthreads();
    if (t < LTHREADS / 32) {
        float v = sred[t];
        #pragma unroll
        for (int off = (LTHREADS / 64); off; off >>= 1)
            v += __shfl_down_sync(0xFFu, v, off);
        if (t == 0) {
            const unsigned long long fx =
                (unsigned long long)__double2ll_rn((double)v * FIXSCALE);
            atomicAdd(&g_acc, fx);
            __threadfence();
            const unsigned ticket = atomicInc(&g_tickets, LBLOCKS - 1);
            if (ticket == LBLOCKS - 1) {
                const unsigned long long total = atomicAdd(&g_acc, 0ULL);
                out[0] = (float)((double)total * (1.0 / FIXSCALE / (double)NPIX));
                __threadfence();
                g_acc = 0ULL;                  // reset for next graph replay
            }
        }
    }
}

extern "C" void kernel_launch(void* const* d_in, const int* in_sizes, int n_in,
                              void* d_out, int out_size) {
    const float* pred    = (const float*)d_in[0];
    const float* target  = (const float*)d_in[1];
    const float* centers = (const float*)d_in[2];
    const float* cw      = (const float*)d_in[3];

    build_kernel<<<BBLOCKS, BTHREADS>>>(centers, cw);
    loss_kernel<<<LBLOCKS, LTHREADS>>>(pred, target, (float*)d_out);
}